// round 4
// baseline (speedup 1.0000x reference)
#include <cuda_runtime.h>
#include <math.h>

#define BSZ 4
#define SEQ 2048
#define HIDDIM 2048
#define NH 16
#define HDIM 128

// Scratch (no allocation allowed): q in [B,H,S,D], ctx in [B,S,H*D]
__device__ float g_q[(size_t)BSZ * NH * SEQ * HDIM];
__device__ float g_ctx[(size_t)BSZ * SEQ * HIDDIM];

// ---------------------------------------------------------------------------
// NT GEMM: C = A[M,K] @ B[N,K]^T   (both K-contiguous)
// mode 0: C row-major [M,N]
// mode 1: scatter into kv cache [B,H,2,S,D] with c=kvsel
// mode 2: scatter into q scratch [B,H,S,D]
// ---------------------------------------------------------------------------
__global__ void __launch_bounds__(256, 2)
gemm_nt(const float* __restrict__ A, const float* __restrict__ B,
        float* __restrict__ C, int M, int N, int K, int mode, int kvsel)
{
    __shared__ float As[16][132];
    __shared__ float Bs[16][132];

    const int tid = threadIdx.x;
    const int tx = tid & 15;
    const int ty = tid >> 4;
    const int bm = blockIdx.y * 128;
    const int bn = blockIdx.x * 128;

    const int lr = tid >> 2;          // 0..63
    const int lc = (tid & 3) << 2;    // 0,4,8,12

    const float* Aptr = A + (size_t)(bm + lr) * K + lc;
    const float* Bptr = B + (size_t)(bn + lr) * K + lc;
    const size_t rowstep = (size_t)64 * K;

    float acc[8][8];
#pragma unroll
    for (int i = 0; i < 8; i++)
#pragma unroll
        for (int j = 0; j < 8; j++) acc[i][j] = 0.f;

    // prologue: load tile 0 into regs
    float4 pa0 = *(const float4*)(Aptr);
    float4 pa1 = *(const float4*)(Aptr + rowstep);
    float4 pb0 = *(const float4*)(Bptr);
    float4 pb1 = *(const float4*)(Bptr + rowstep);

    const int T = K >> 4;
    for (int kt = 0; kt < T; kt++) {
        // regs -> smem (A,B transposed to [k][row])
        As[lc + 0][lr] = pa0.x; As[lc + 1][lr] = pa0.y;
        As[lc + 2][lr] = pa0.z; As[lc + 3][lr] = pa0.w;
        As[lc + 0][lr + 64] = pa1.x; As[lc + 1][lr + 64] = pa1.y;
        As[lc + 2][lr + 64] = pa1.z; As[lc + 3][lr + 64] = pa1.w;
        Bs[lc + 0][lr] = pb0.x; Bs[lc + 1][lr] = pb0.y;
        Bs[lc + 2][lr] = pb0.z; Bs[lc + 3][lr] = pb0.w;
        Bs[lc + 0][lr + 64] = pb1.x; Bs[lc + 1][lr + 64] = pb1.y;
        Bs[lc + 2][lr + 64] = pb1.z; Bs[lc + 3][lr + 64] = pb1.w;
        __syncthreads();

        if (kt + 1 < T) {   // prefetch next tile (overlaps compute below)
            const float* An = Aptr + (size_t)(kt + 1) * 16;
            const float* Bn = Bptr + (size_t)(kt + 1) * 16;
            pa0 = *(const float4*)(An);
            pa1 = *(const float4*)(An + rowstep);
            pb0 = *(const float4*)(Bn);
            pb1 = *(const float4*)(Bn + rowstep);
        }

#pragma unroll
        for (int kk = 0; kk < 16; kk++) {
            float4 a0 = *(const float4*)&As[kk][ty * 4];
            float4 a1 = *(const float4*)&As[kk][64 + ty * 4];
            float4 b0 = *(const float4*)&Bs[kk][tx * 4];
            float4 b1 = *(const float4*)&Bs[kk][64 + tx * 4];
            float a[8] = {a0.x, a0.y, a0.z, a0.w, a1.x, a1.y, a1.z, a1.w};
            float b[8] = {b0.x, b0.y, b0.z, b0.w, b1.x, b1.y, b1.z, b1.w};
#pragma unroll
            for (int i = 0; i < 8; i++)
#pragma unroll
                for (int j = 0; j < 8; j++)
                    acc[i][j] += a[i] * b[j];
        }
        __syncthreads();
    }

    // epilogue
#pragma unroll
    for (int ii = 0; ii < 8; ii++) {
        int mrow = bm + ((ii < 4) ? (ty * 4 + ii) : (64 + ty * 4 + (ii - 4)));
#pragma unroll
        for (int jh = 0; jh < 2; jh++) {
            int ncol = bn + jh * 64 + tx * 4;
            float4 v = make_float4(acc[ii][jh * 4 + 0], acc[ii][jh * 4 + 1],
                                   acc[ii][jh * 4 + 2], acc[ii][jh * 4 + 3]);
            size_t addr;
            if (mode == 0) {
                addr = (size_t)mrow * N + ncol;
            } else {
                int b = mrow >> 11;          // / SEQ
                int s = mrow & 2047;
                int h = ncol >> 7;           // / HDIM
                int d = ncol & 127;
                if (mode == 1)
                    addr = ((((size_t)b * NH + h) * 2 + kvsel) * SEQ + s) * HDIM + d;
                else
                    addr = (((size_t)b * NH + h) * SEQ + s) * HDIM + d;
            }
            *(float4*)(C + addr) = v;
        }
    }
}

// ---------------------------------------------------------------------------
// Flash attention: causal, 64x64 tiles, online softmax.
// Q: [B,H,S,D] scratch.  KV: kv-cache region of d_out [B,H,2,S,D].
// ctx out: [B,S,H*D] so the output projection is a plain NT GEMM.
// ---------------------------------------------------------------------------
__global__ void __launch_bounds__(256)
flash_attn(const float* __restrict__ Qg, const float* __restrict__ KVg,
           float* __restrict__ ctx)
{
    extern __shared__ float sm[];
    float* sQ = sm;                 // [64][128]
    float* sK = sQ + 64 * 128;      // [64][128] XOR-swizzled
    float* sV = sK + 64 * 128;      // [64][128]
    float* sP = sV + 64 * 128;      // [64][68]

    const int tid = threadIdx.x;
    const int tx = tid & 15;
    const int ty = tid >> 4;
    const int qt = blockIdx.x;      // q tile 0..31
    const int bh = blockIdx.y;      // b*NH + h, 0..63

    const float* qsrc = Qg + ((size_t)bh * SEQ + (size_t)qt * 64) * HDIM;
    const float* kb = KVg + (size_t)bh * 2 * SEQ * HDIM;
    const float* vb = kb + (size_t)SEQ * HDIM;

    // load Q tile (plain row-major, reads are lane-broadcast later)
    for (int f = tid; f < 64 * 32; f += 256) {
        int r = f >> 5, c4 = f & 31;
        *(float4*)&sQ[r * 128 + c4 * 4] = *(const float4*)(qsrc + r * 128 + c4 * 4);
    }

    float m_i[4], l_i[4], o[4][8];
#pragma unroll
    for (int i = 0; i < 4; i++) {
        m_i[i] = -INFINITY; l_i[i] = 0.f;
#pragma unroll
        for (int c = 0; c < 8; c++) o[i][c] = 0.f;
    }

    const float scale = 0.08838834764831845f;   // 1/sqrt(128)
    const int txl = tx & 7;

    for (int kt = 0; kt <= qt; kt++) {
        __syncthreads();   // prior-iter smem reads complete before overwrite
        const float* kg = kb + (size_t)kt * 64 * HDIM;
        const float* vg = vb + (size_t)kt * 64 * HDIM;
        for (int f = tid; f < 64 * 32; f += 256) {
            int r = f >> 5, c4 = f & 31;
            int p4 = c4 ^ (r & 7);   // swizzle so column-of-rows reads are conflict-free
            *(float4*)&sK[r * 128 + p4 * 4] = *(const float4*)(kg + r * 128 + c4 * 4);
            *(float4*)&sV[r * 128 + c4 * 4] = *(const float4*)(vg + r * 128 + c4 * 4);
        }
        __syncthreads();

        // scores: thread owns q-rows ty*4+i, k-cols tx+16*j
        float s[4][4];
#pragma unroll
        for (int i = 0; i < 4; i++)
#pragma unroll
            for (int j = 0; j < 4; j++) s[i][j] = 0.f;

#pragma unroll 8
        for (int d4 = 0; d4 < 32; d4++) {
            float4 qv[4], kv[4];
#pragma unroll
            for (int i = 0; i < 4; i++)
                qv[i] = *(const float4*)&sQ[(ty * 4 + i) * 128 + d4 * 4];
#pragma unroll
            for (int j = 0; j < 4; j++) {
                int r = tx + 16 * j;
                kv[j] = *(const float4*)&sK[r * 128 + ((d4 ^ txl) * 4)];
            }
#pragma unroll
            for (int i = 0; i < 4; i++)
#pragma unroll
                for (int j = 0; j < 4; j++)
                    s[i][j] += qv[i].x * kv[j].x + qv[i].y * kv[j].y +
                               qv[i].z * kv[j].z + qv[i].w * kv[j].w;
        }

        // scale + causal mask (only diagonal tile needs masking)
#pragma unroll
        for (int i = 0; i < 4; i++) {
            int qg = qt * 64 + ty * 4 + i;
#pragma unroll
            for (int j = 0; j < 4; j++) {
                s[i][j] *= scale;
                if (kt == qt) {
                    int kgidx = kt * 64 + tx + 16 * j;
                    if (kgidx > qg) s[i][j] = -INFINITY;
                }
            }
        }

        // online softmax (row reductions across the 16 tx lanes = half-warp)
#pragma unroll
        for (int i = 0; i < 4; i++) {
            float rmax = fmaxf(fmaxf(s[i][0], s[i][1]), fmaxf(s[i][2], s[i][3]));
#pragma unroll
            for (int off = 8; off >= 1; off >>= 1)
                rmax = fmaxf(rmax, __shfl_xor_sync(0xffffffffu, rmax, off, 16));
            float mnew = fmaxf(m_i[i], rmax);
            float corr = __expf(m_i[i] - mnew);
            float rsum = 0.f;
#pragma unroll
            for (int j = 0; j < 4; j++) {
                s[i][j] = __expf(s[i][j] - mnew);
                rsum += s[i][j];
            }
#pragma unroll
            for (int off = 8; off >= 1; off >>= 1)
                rsum += __shfl_xor_sync(0xffffffffu, rsum, off, 16);
            l_i[i] = l_i[i] * corr + rsum;
            m_i[i] = mnew;
#pragma unroll
            for (int c = 0; c < 8; c++) o[i][c] *= corr;
        }

        // write P tile
#pragma unroll
        for (int i = 0; i < 4; i++)
#pragma unroll
            for (int j = 0; j < 4; j++)
                sP[(ty * 4 + i) * 68 + tx + 16 * j] = s[i][j];
        __syncthreads();

        // O += P @ V : thread owns cols tx*4..+3 and 64+tx*4..+3
#pragma unroll 8
        for (int kr = 0; kr < 64; kr++) {
            float4 v0 = *(const float4*)&sV[kr * 128 + tx * 4];
            float4 v1 = *(const float4*)&sV[kr * 128 + 64 + tx * 4];
#pragma unroll
            for (int i = 0; i < 4; i++) {
                float p = sP[(ty * 4 + i) * 68 + kr];
                o[i][0] += p * v0.x; o[i][1] += p * v0.y;
                o[i][2] += p * v0.z; o[i][3] += p * v0.w;
                o[i][4] += p * v1.x; o[i][5] += p * v1.y;
                o[i][6] += p * v1.z; o[i][7] += p * v1.w;
            }
        }
    }

    // epilogue: ctx[b, s, h*128 + d]
    const int b = bh >> 4;
    const int h = bh & 15;
#pragma unroll
    for (int i = 0; i < 4; i++) {
        float inv = 1.f / l_i[i];
        int srow = qt * 64 + ty * 4 + i;
        size_t base = ((size_t)b * SEQ + srow) * HIDDIM + (size_t)h * HDIM;
        float4 v0 = make_float4(o[i][0] * inv, o[i][1] * inv, o[i][2] * inv, o[i][3] * inv);
        float4 v1 = make_float4(o[i][4] * inv, o[i][5] * inv, o[i][6] * inv, o[i][7] * inv);
        *(float4*)(ctx + base + tx * 4) = v0;
        *(float4*)(ctx + base + 64 + tx * 4) = v1;
    }
}

// ---------------------------------------------------------------------------
extern "C" void kernel_launch(void* const* d_in, const int* in_sizes, int n_in,
                              void* d_out, int out_size)
{
    const float* x  = (const float*)d_in[0];
    const float* Wq = (const float*)d_in[1];
    const float* Wk = (const float*)d_in[2];
    const float* Wv = (const float*)d_in[3];
    const float* Wo = (const float*)d_in[4];

    float* out = (float*)d_out;                                  // [B,S,HID]
    float* kv  = out + (size_t)BSZ * SEQ * HIDDIM;               // [B,H,2,S,D]

    float *gq, *gctx;
    cudaGetSymbolAddress((void**)&gq, g_q);
    cudaGetSymbolAddress((void**)&gctx, g_ctx);

    const int M = BSZ * SEQ;     // 8192
    dim3 ggrid(HIDDIM / 128, M / 128);   // (16, 64)

    // QKV projections
    gemm_nt<<<ggrid, 256>>>(x, Wq, gq, M, HIDDIM, HIDDIM, 2, 0);
    gemm_nt<<<ggrid, 256>>>(x, Wk, kv, M, HIDDIM, HIDDIM, 1, 0);
    gemm_nt<<<ggrid, 256>>>(x, Wv, kv, M, HIDDIM, HIDDIM, 1, 1);

    // flash attention
    const int smem = (3 * 64 * 128 + 64 * 68) * sizeof(float);   // 115712 B
    cudaFuncSetAttribute(flash_attn, cudaFuncAttributeMaxDynamicSharedMemorySize, smem);
    flash_attn<<<dim3(SEQ / 64, BSZ * NH), 256, smem>>>(gq, kv, gctx);

    // output projection
    gemm_nt<<<ggrid, 256>>>(gctx, Wo, out, M, HIDDIM, HIDDIM, 0, 0);
}

// round 11
// speedup vs baseline: 2.6949x; 2.6949x over previous
#include <cuda_runtime.h>
#include <cuda_bf16.h>
#include <math.h>
#include <stdint.h>

#define BSZ 4
#define SEQ 2048
#define HIDDIM 2048
#define NH 16
#define HDIM 128
#define MTOT (BSZ * SEQ)   // 8192

// ---------------------------------------------------------------------------
// Scratch (static __device__ — no allocations allowed)
// ---------------------------------------------------------------------------
__device__ float g_q[(size_t)BSZ * NH * SEQ * HDIM];                 // [B,H,S,D]
__device__ __nv_bfloat16 g_xhi[(size_t)MTOT * HIDDIM];
__device__ __nv_bfloat16 g_xlo[(size_t)MTOT * HIDDIM];
__device__ __nv_bfloat16 g_whi[(size_t)4 * HIDDIM * HIDDIM];
__device__ __nv_bfloat16 g_wlo[(size_t)4 * HIDDIM * HIDDIM];
__device__ __nv_bfloat16 g_chi[(size_t)MTOT * HIDDIM];               // ctx hi
__device__ __nv_bfloat16 g_clo[(size_t)MTOT * HIDDIM];               // ctx lo

// ---------------------------------------------------------------------------
// Portable (compute_80+) tensor-core helpers: mma.sync / ldmatrix / cp.async
// ---------------------------------------------------------------------------
__device__ __forceinline__ uint32_t smem_u32(const void* p) {
    uint32_t a;
    asm("{ .reg .u64 t; cvta.to.shared.u64 t, %1; cvt.u32.u64 %0, t; }" : "=r"(a) : "l"(p));
    return a;
}

__device__ __forceinline__ void cp_async16(uint32_t dst, const void* src) {
    asm volatile("cp.async.cg.shared.global [%0], [%1], 16;" :: "r"(dst), "l"(src) : "memory");
}
__device__ __forceinline__ void cp_commit() {
    asm volatile("cp.async.commit_group;" ::: "memory");
}
template <int N>
__device__ __forceinline__ void cp_wait() {
    asm volatile("cp.async.wait_group %0;" :: "n"(N) : "memory");
}

__device__ __forceinline__ void ldsm_x4(uint32_t* r, uint32_t addr) {
    asm volatile("ldmatrix.sync.aligned.m8n8.x4.shared.b16 {%0,%1,%2,%3}, [%4];"
                 : "=r"(r[0]), "=r"(r[1]), "=r"(r[2]), "=r"(r[3]) : "r"(addr));
}

// D = A@B + D  (m16n8k16, bf16 in, fp32 accum)
__device__ __forceinline__ void mma_16816(float* c, const uint32_t* a, const uint32_t* b) {
    asm volatile(
        "mma.sync.aligned.m16n8k16.row.col.f32.bf16.bf16.f32 "
        "{%0,%1,%2,%3}, {%4,%5,%6,%7}, {%8,%9}, {%0,%1,%2,%3};"
        : "+f"(c[0]), "+f"(c[1]), "+f"(c[2]), "+f"(c[3])
        : "r"(a[0]), "r"(a[1]), "r"(a[2]), "r"(a[3]), "r"(b[0]), "r"(b[1]));
}

// ---------------------------------------------------------------------------
// fp32 -> bf16 hi/lo split (vectorized, memory-bound)
// ---------------------------------------------------------------------------
__global__ void split_f32(const float* __restrict__ src, __nv_bfloat16* __restrict__ hi,
                          __nv_bfloat16* __restrict__ lo, int n4)
{
    int i = blockIdx.x * blockDim.x + threadIdx.x;
    if (i >= n4) return;
    float4 v = ((const float4*)src)[i];
    float a[4] = {v.x, v.y, v.z, v.w};
    unsigned short hs[4], ls[4];
#pragma unroll
    for (int t = 0; t < 4; t++) {
        __nv_bfloat16 h = __float2bfloat16_rn(a[t]);
        float hf = __bfloat162float(h);
        __nv_bfloat16 l = __float2bfloat16_rn(a[t] - hf);
        hs[t] = __bfloat16_as_ushort(h);
        ls[t] = __bfloat16_as_ushort(l);
    }
    ((uint2*)hi)[i] = make_uint2((uint32_t)hs[0] | ((uint32_t)hs[1] << 16),
                                 (uint32_t)hs[2] | ((uint32_t)hs[3] << 16));
    ((uint2*)lo)[i] = make_uint2((uint32_t)ls[0] | ((uint32_t)ls[1] << 16),
                                 (uint32_t)ls[2] | ((uint32_t)ls[3] << 16));
}

// ---------------------------------------------------------------------------
// mma.sync bf16x3 NT GEMM: C = (Ahi+Alo)[M,K] @ (Bhi+Blo)[N,K]^T, fp32 out.
// 128x128 block tile, 8 warps of 64x32, K-chunks of 64 bf16 (128B rows,
// XOR-swizzled, conflict-free ldmatrix), cp.async double buffering.
// mode 0: row-major [M,N]; mode 1: kv cache [B,H,2,S,D]; mode 2: q [B,H,S,D]
// ---------------------------------------------------------------------------
#define KC 64
#define TILE_B  (128 * 128)       // one 128-row x 128-byte tensor tile
#define STAGE_B (4 * TILE_B)      // Ahi, Alo, Bhi, Blo  = 64 KB
#define NCHUNK  (HIDDIM / KC)     // 32

__global__ void __launch_bounds__(256, 1)
gemm_mma(const __nv_bfloat16* __restrict__ Ahi, const __nv_bfloat16* __restrict__ Alo,
         const __nv_bfloat16* __restrict__ Bhi, const __nv_bfloat16* __restrict__ Blo,
         float* __restrict__ C, int mode, int kvsel)
{
    extern __shared__ char dsm[];
    const int tid  = threadIdx.x;
    const int wid  = tid >> 5;
    const int lane = tid & 31;
    const int wm   = wid >> 2;          // 0..1  (64-row slab)
    const int wn   = wid & 3;           // 0..3  (32-col slab)
    const int bm = blockIdx.y * 128;
    const int bn = blockIdx.x * 128;
    const uint32_t smb = smem_u32(dsm);

    float acc[4][4][4];
#pragma unroll
    for (int mi = 0; mi < 4; mi++)
#pragma unroll
        for (int ni = 0; ni < 4; ni++)
#pragma unroll
            for (int t = 0; t < 4; t++) acc[mi][ni][t] = 0.f;

    // per-thread cp.async slots: idx = tid + it*256 -> row=idx>>3, chunk=idx&7
    const int lr = tid >> 3;            // base row (stride 32 over 4 its)
    const int lc = tid & 7;             // 16B chunk 0..7
    const int lsw = ((lc ^ (lr & 7)) << 4);

    auto issue_stage = [&](int st, int kc) {
        char* s = dsm + st * STAGE_B;
        const size_t kb = (size_t)kc * KC;
#pragma unroll
        for (int it = 0; it < 4; it++) {
            int r = lr + it * 32;
            int sw = ((lc ^ (r & 7)) << 4);
            uint32_t so = smem_u32(s) + r * 128 + sw;
            size_t ga = (size_t)(bm + r) * HIDDIM + kb + lc * 8;
            size_t gb = (size_t)(bn + r) * HIDDIM + kb + lc * 8;
            cp_async16(so + 0 * TILE_B, Ahi + ga);
            cp_async16(so + 1 * TILE_B, Alo + ga);
            cp_async16(so + 2 * TILE_B, Bhi + gb);
            cp_async16(so + 3 * TILE_B, Blo + gb);
        }
        cp_commit();
    };
    (void)lsw;

    issue_stage(0, 0);

    for (int kc = 0; kc < NCHUNK; kc++) {
        const int st = kc & 1;
        if (kc + 1 < NCHUNK) {
            issue_stage(st ^ 1, kc + 1);
            cp_wait<1>();
        } else {
            cp_wait<0>();
        }
        __syncthreads();

        const uint32_t sb = smb + st * STAGE_B;
        // A rows this warp touches: wm*64 + mi*16 + (lane&15)
        const int arow_l = (lane & 15);
        const int koff_l = (lane >> 4);      // 0/1 -> +16B within k-step

#pragma unroll
        for (int ks = 0; ks < 4; ks++) {     // 4 k-steps of 16 bf16
            const int chunk = ks * 2 + koff_l;
            uint32_t ahi[4][4], alo[4][4];
#pragma unroll
            for (int mi = 0; mi < 4; mi++) {
                int r = wm * 64 + mi * 16 + arow_l;
                uint32_t off = (uint32_t)(r * 128 + ((chunk ^ (r & 7)) << 4));
                ldsm_x4(ahi[mi], sb + 0 * TILE_B + off);
                ldsm_x4(alo[mi], sb + 1 * TILE_B + off);
            }
            uint32_t bhi[4][2], blo[4][2];
#pragma unroll
            for (int g = 0; g < 2; g++) {
                int r = wn * 32 + g * 16 + arow_l;
                uint32_t off = (uint32_t)(r * 128 + ((chunk ^ (r & 7)) << 4));
                uint32_t t[4];
                ldsm_x4(t, sb + 2 * TILE_B + off);
                bhi[g * 2 + 0][0] = t[0]; bhi[g * 2 + 1][0] = t[1];
                bhi[g * 2 + 0][1] = t[2]; bhi[g * 2 + 1][1] = t[3];
                ldsm_x4(t, sb + 3 * TILE_B + off);
                blo[g * 2 + 0][0] = t[0]; blo[g * 2 + 1][0] = t[1];
                blo[g * 2 + 0][1] = t[2]; blo[g * 2 + 1][1] = t[3];
            }
#pragma unroll
            for (int mi = 0; mi < 4; mi++)
#pragma unroll
                for (int ni = 0; ni < 4; ni++) {
                    mma_16816(acc[mi][ni], ahi[mi], bhi[ni]);   // hi*hi
                    mma_16816(acc[mi][ni], ahi[mi], blo[ni]);   // hi*lo
                    mma_16816(acc[mi][ni], alo[mi], bhi[ni]);   // lo*hi
                }
        }
        __syncthreads();   // all warps done reading stage st before it is refilled
    }

    // epilogue: c0,c1 -> row=lane/4, cols (lane%4)*2,+1 ; c2,c3 -> row+8
#pragma unroll
    for (int mi = 0; mi < 4; mi++) {
        const int row0 = bm + wm * 64 + mi * 16 + (lane >> 2);
#pragma unroll
        for (int half = 0; half < 2; half++) {
            const int row = row0 + half * 8;
            const int b = row >> 11, s = row & 2047;
#pragma unroll
            for (int ni = 0; ni < 4; ni++) {
                const int col = bn + wn * 32 + ni * 8 + (lane & 3) * 2;
                size_t addr;
                if (mode == 0) {
                    addr = (size_t)row * HIDDIM + col;
                } else {
                    int h = col >> 7, d = col & 127;
                    if (mode == 1)
                        addr = ((((size_t)b * NH + h) * 2 + kvsel) * SEQ + s) * HDIM + d;
                    else
                        addr = (((size_t)b * NH + h) * SEQ + s) * HDIM + d;
                }
                float2 v = make_float2(acc[mi][ni][half * 2 + 0], acc[mi][ni][half * 2 + 1]);
                *(float2*)(C + addr) = v;
            }
        }
    }
}

// ---------------------------------------------------------------------------
// Flash attention: causal, 64x64 tiles, online softmax (fp32).
// ctx written as bf16 hi/lo directly (feeds the mma output projection).
// ---------------------------------------------------------------------------
__global__ void __launch_bounds__(256)
flash_attn(const float* __restrict__ Qg, const float* __restrict__ KVg,
           __nv_bfloat16* __restrict__ chi, __nv_bfloat16* __restrict__ clo)
{
    extern __shared__ float sm[];
    float* sQ = sm;                 // [64][128]
    float* sK = sQ + 64 * 128;      // [64][128] XOR-swizzled
    float* sV = sK + 64 * 128;      // [64][128]
    float* sP = sV + 64 * 128;      // [64][68]

    const int tid = threadIdx.x;
    const int tx = tid & 15;
    const int ty = tid >> 4;
    const int qt = blockIdx.x;
    const int bh = blockIdx.y;

    const float* qsrc = Qg + ((size_t)bh * SEQ + (size_t)qt * 64) * HDIM;
    const float* kb = KVg + (size_t)bh * 2 * SEQ * HDIM;
    const float* vb = kb + (size_t)SEQ * HDIM;

    for (int f = tid; f < 64 * 32; f += 256) {
        int r = f >> 5, c4 = f & 31;
        *(float4*)&sQ[r * 128 + c4 * 4] = *(const float4*)(qsrc + r * 128 + c4 * 4);
    }

    float m_i[4], l_i[4], o[4][8];
#pragma unroll
    for (int i = 0; i < 4; i++) {
        m_i[i] = -INFINITY; l_i[i] = 0.f;
#pragma unroll
        for (int c = 0; c < 8; c++) o[i][c] = 0.f;
    }

    const float scale = 0.08838834764831845f;
    const int txl = tx & 7;

    for (int kt = 0; kt <= qt; kt++) {
        __syncthreads();
        const float* kg = kb + (size_t)kt * 64 * HDIM;
        const float* vg = vb + (size_t)kt * 64 * HDIM;
        for (int f = tid; f < 64 * 32; f += 256) {
            int r = f >> 5, c4 = f & 31;
            int p4 = c4 ^ (r & 7);
            *(float4*)&sK[r * 128 + p4 * 4] = *(const float4*)(kg + r * 128 + c4 * 4);
            *(float4*)&sV[r * 128 + c4 * 4] = *(const float4*)(vg + r * 128 + c4 * 4);
        }
        __syncthreads();

        float s[4][4];
#pragma unroll
        for (int i = 0; i < 4; i++)
#pragma unroll
            for (int j = 0; j < 4; j++) s[i][j] = 0.f;

#pragma unroll 8
        for (int d4 = 0; d4 < 32; d4++) {
            float4 qv[4], kv[4];
#pragma unroll
            for (int i = 0; i < 4; i++)
                qv[i] = *(const float4*)&sQ[(ty * 4 + i) * 128 + d4 * 4];
#pragma unroll
            for (int j = 0; j < 4; j++) {
                int r = tx + 16 * j;
                kv[j] = *(const float4*)&sK[r * 128 + ((d4 ^ txl) * 4)];
            }
#pragma unroll
            for (int i = 0; i < 4; i++)
#pragma unroll
                for (int j = 0; j < 4; j++)
                    s[i][j] += qv[i].x * kv[j].x + qv[i].y * kv[j].y +
                               qv[i].z * kv[j].z + qv[i].w * kv[j].w;
        }

#pragma unroll
        for (int i = 0; i < 4; i++) {
            int qg = qt * 64 + ty * 4 + i;
#pragma unroll
            for (int j = 0; j < 4; j++) {
                s[i][j] *= scale;
                if (kt == qt) {
                    int kgidx = kt * 64 + tx + 16 * j;
                    if (kgidx > qg) s[i][j] = -INFINITY;
                }
            }
        }

#pragma unroll
        for (int i = 0; i < 4; i++) {
            float rmax = fmaxf(fmaxf(s[i][0], s[i][1]), fmaxf(s[i][2], s[i][3]));
#pragma unroll
            for (int off = 8; off >= 1; off >>= 1)
                rmax = fmaxf(rmax, __shfl_xor_sync(0xffffffffu, rmax, off, 16));
            float mnew = fmaxf(m_i[i], rmax);
            float corr = __expf(m_i[i] - mnew);
            float rsum = 0.f;
#pragma unroll
            for (int j = 0; j < 4; j++) {
                s[i][j] = __expf(s[i][j] - mnew);
                rsum += s[i][j];
            }
#pragma unroll
            for (int off = 8; off >= 1; off >>= 1)
                rsum += __shfl_xor_sync(0xffffffffu, rsum, off, 16);
            l_i[i] = l_i[i] * corr + rsum;
            m_i[i] = mnew;
#pragma unroll
            for (int c = 0; c < 8; c++) o[i][c] *= corr;
        }

#pragma unroll
        for (int i = 0; i < 4; i++)
#pragma unroll
            for (int j = 0; j < 4; j++)
                sP[(ty * 4 + i) * 68 + tx + 16 * j] = s[i][j];
        __syncthreads();

#pragma unroll 8
        for (int kr = 0; kr < 64; kr++) {
            float4 v0 = *(const float4*)&sV[kr * 128 + tx * 4];
            float4 v1 = *(const float4*)&sV[kr * 128 + 64 + tx * 4];
#pragma unroll
            for (int i = 0; i < 4; i++) {
                float p = sP[(ty * 4 + i) * 68 + kr];
                o[i][0] += p * v0.x; o[i][1] += p * v0.y;
                o[i][2] += p * v0.z; o[i][3] += p * v0.w;
                o[i][4] += p * v1.x; o[i][5] += p * v1.y;
                o[i][6] += p * v1.z; o[i][7] += p * v1.w;
            }
        }
    }

    // epilogue: ctx[b, s, h*128 + d] split into bf16 hi/lo
    const int b = bh >> 4;
    const int h = bh & 15;
#pragma unroll
    for (int i = 0; i < 4; i++) {
        float inv = 1.f / l_i[i];
        int srow = qt * 64 + ty * 4 + i;
        size_t base = ((size_t)b * SEQ + srow) * HIDDIM + (size_t)h * HDIM;
#pragma unroll
        for (int seg = 0; seg < 2; seg++) {
            unsigned short hs[4], ls[4];
#pragma unroll
            for (int t = 0; t < 4; t++) {
                float v = o[i][seg * 4 + t] * inv;
                __nv_bfloat16 hh = __float2bfloat16_rn(v);
                float hf = __bfloat162float(hh);
                __nv_bfloat16 ll = __float2bfloat16_rn(v - hf);
                hs[t] = __bfloat16_as_ushort(hh);
                ls[t] = __bfloat16_as_ushort(ll);
            }
            size_t off = base + seg * 64 + tx * 4;
            *(uint2*)(chi + off) = make_uint2((uint32_t)hs[0] | ((uint32_t)hs[1] << 16),
                                              (uint32_t)hs[2] | ((uint32_t)hs[3] << 16));
            *(uint2*)(clo + off) = make_uint2((uint32_t)ls[0] | ((uint32_t)ls[1] << 16),
                                              (uint32_t)ls[2] | ((uint32_t)ls[3] << 16));
        }
    }
}

// ---------------------------------------------------------------------------
extern "C" void kernel_launch(void* const* d_in, const int* in_sizes, int n_in,
                              void* d_out, int out_size)
{
    const float* x  = (const float*)d_in[0];
    const float* Wq = (const float*)d_in[1];
    const float* Wk = (const float*)d_in[2];
    const float* Wv = (const float*)d_in[3];
    const float* Wo = (const float*)d_in[4];

    float* out = (float*)d_out;                          // [B,S,HID]
    float* kv  = out + (size_t)BSZ * SEQ * HIDDIM;       // [B,H,2,S,D]

    float *gq;
    __nv_bfloat16 *xhi, *xlo, *whi, *wlo, *chi, *clo;
    cudaGetSymbolAddress((void**)&gq,  g_q);
    cudaGetSymbolAddress((void**)&xhi, g_xhi);
    cudaGetSymbolAddress((void**)&xlo, g_xlo);
    cudaGetSymbolAddress((void**)&whi, g_whi);
    cudaGetSymbolAddress((void**)&wlo, g_wlo);
    cudaGetSymbolAddress((void**)&chi, g_chi);
    cudaGetSymbolAddress((void**)&clo, g_clo);

    const size_t WN = (size_t)HIDDIM * HIDDIM;

    // splits
    {
        int n4x = (int)((size_t)MTOT * HIDDIM / 4);
        split_f32<<<(n4x + 255) / 256, 256>>>(x, xhi, xlo, n4x);
        int n4w = (int)(WN / 4);
        split_f32<<<(n4w + 255) / 256, 256>>>(Wq, whi + 0 * WN, wlo + 0 * WN, n4w);
        split_f32<<<(n4w + 255) / 256, 256>>>(Wk, whi + 1 * WN, wlo + 1 * WN, n4w);
        split_f32<<<(n4w + 255) / 256, 256>>>(Wv, whi + 2 * WN, wlo + 2 * WN, n4w);
        split_f32<<<(n4w + 255) / 256, 256>>>(Wo, whi + 3 * WN, wlo + 3 * WN, n4w);
    }

    // mma.sync GEMMs (double-buffered smem: 128 KB)
    const int gsmem = 2 * STAGE_B;
    cudaFuncSetAttribute(gemm_mma, cudaFuncAttributeMaxDynamicSharedMemorySize, gsmem);
    dim3 ggrid(HIDDIM / 128, MTOT / 128);                // (16, 64)
    gemm_mma<<<ggrid, 256, gsmem>>>(xhi, xlo, whi + 0 * WN, wlo + 0 * WN, gq, 2, 0);
    gemm_mma<<<ggrid, 256, gsmem>>>(xhi, xlo, whi + 1 * WN, wlo + 1 * WN, kv, 1, 0);
    gemm_mma<<<ggrid, 256, gsmem>>>(xhi, xlo, whi + 2 * WN, wlo + 2 * WN, kv, 1, 1);

    // flash attention (fp32)
    const int asmem = (3 * 64 * 128 + 64 * 68) * sizeof(float);   // 115712 B
    cudaFuncSetAttribute(flash_attn, cudaFuncAttributeMaxDynamicSharedMemorySize, asmem);
    flash_attn<<<dim3(SEQ / 64, BSZ * NH), 256, asmem>>>(gq, kv, chi, clo);

    // output projection
    gemm_mma<<<ggrid, 256, gsmem>>>(chi, clo, whi + 3 * WN, wlo + 3 * WN, out, 0, 0);
}

// round 12
// speedup vs baseline: 3.9236x; 1.4559x over previous
#include <cuda_runtime.h>
#include <cuda_bf16.h>
#include <math.h>
#include <stdint.h>

#define BSZ 4
#define SEQ 2048
#define HIDDIM 2048
#define NH 16
#define HDIM 128
#define MTOT (BSZ * SEQ)   // 8192
#define QKSCALE 0.08838834764831845f

// ---------------------------------------------------------------------------
// Scratch (static __device__ — no allocations allowed)
// ---------------------------------------------------------------------------
__device__ __nv_bfloat16 g_xhi[(size_t)MTOT * HIDDIM];
__device__ __nv_bfloat16 g_xlo[(size_t)MTOT * HIDDIM];
__device__ __nv_bfloat16 g_whi[(size_t)4 * HIDDIM * HIDDIM];
__device__ __nv_bfloat16 g_wlo[(size_t)4 * HIDDIM * HIDDIM];
__device__ __nv_bfloat16 g_chi[(size_t)MTOT * HIDDIM];               // ctx hi
__device__ __nv_bfloat16 g_clo[(size_t)MTOT * HIDDIM];               // ctx lo
__device__ __nv_bfloat16 g_qhi[(size_t)MTOT * HIDDIM];               // [B,H,S,D] scaled
__device__ __nv_bfloat16 g_qlo[(size_t)MTOT * HIDDIM];
__device__ __nv_bfloat16 g_khi[(size_t)MTOT * HIDDIM];               // [B,H,S,D]
__device__ __nv_bfloat16 g_klo[(size_t)MTOT * HIDDIM];
__device__ __nv_bfloat16 g_vhi[(size_t)MTOT * HIDDIM];
__device__ __nv_bfloat16 g_vlo[(size_t)MTOT * HIDDIM];

// ---------------------------------------------------------------------------
// Portable (compute_80+) tensor-core helpers
// ---------------------------------------------------------------------------
__device__ __forceinline__ uint32_t smem_u32(const void* p) {
    uint32_t a;
    asm("{ .reg .u64 t; cvta.to.shared.u64 t, %1; cvt.u32.u64 %0, t; }" : "=r"(a) : "l"(p));
    return a;
}
__device__ __forceinline__ void cp_async16(uint32_t dst, const void* src) {
    asm volatile("cp.async.cg.shared.global [%0], [%1], 16;" :: "r"(dst), "l"(src) : "memory");
}
__device__ __forceinline__ void cp_commit() {
    asm volatile("cp.async.commit_group;" ::: "memory");
}
template <int N>
__device__ __forceinline__ void cp_wait() {
    asm volatile("cp.async.wait_group %0;" :: "n"(N) : "memory");
}
__device__ __forceinline__ void ldsm_x4(uint32_t* r, uint32_t addr) {
    asm volatile("ldmatrix.sync.aligned.m8n8.x4.shared.b16 {%0,%1,%2,%3}, [%4];"
                 : "=r"(r[0]), "=r"(r[1]), "=r"(r[2]), "=r"(r[3]) : "r"(addr));
}
__device__ __forceinline__ void ldsm_x4_t(uint32_t* r, uint32_t addr) {
    asm volatile("ldmatrix.sync.aligned.m8n8.x4.trans.shared.b16 {%0,%1,%2,%3}, [%4];"
                 : "=r"(r[0]), "=r"(r[1]), "=r"(r[2]), "=r"(r[3]) : "r"(addr));
}
__device__ __forceinline__ void mma_16816(float* c, const uint32_t* a, const uint32_t* b) {
    asm volatile(
        "mma.sync.aligned.m16n8k16.row.col.f32.bf16.bf16.f32 "
        "{%0,%1,%2,%3}, {%4,%5,%6,%7}, {%8,%9}, {%0,%1,%2,%3};"
        : "+f"(c[0]), "+f"(c[1]), "+f"(c[2]), "+f"(c[3])
        : "r"(a[0]), "r"(a[1]), "r"(a[2]), "r"(a[3]), "r"(b[0]), "r"(b[1]));
}

// split two floats -> bf16x2 hi word + bf16x2 lo word
__device__ __forceinline__ void split2(float a, float b, uint32_t& hi, uint32_t& lo) {
    __nv_bfloat16 ha = __float2bfloat16_rn(a), hb = __float2bfloat16_rn(b);
    __nv_bfloat16 la = __float2bfloat16_rn(a - __bfloat162float(ha));
    __nv_bfloat16 lb = __float2bfloat16_rn(b - __bfloat162float(hb));
    hi = (uint32_t)__bfloat16_as_ushort(ha) | ((uint32_t)__bfloat16_as_ushort(hb) << 16);
    lo = (uint32_t)__bfloat16_as_ushort(la) | ((uint32_t)__bfloat16_as_ushort(lb) << 16);
}

// FFMA-pipe exp (no MUFU): exp(x), x <= 0, handles -inf. rel err ~2e-6.
__device__ __forceinline__ float fexp(float x) {
    float t = x * 1.4426950408889634f;        // log2(e)
    t = fmaxf(t, -126.0f);
    float fi = t + 12582912.0f;               // round-to-nearest int
    int i = __float_as_int(fi) - 0x4B400000;
    float r = t - (fi - 12582912.0f);         // r in [-0.5, 0.5]
    float y = r * 0.6931471805599453f;        // r*ln2 in [-0.347, 0.347]
    float p = 0.008333333333f;
    p = fmaf(p, y, 0.041666666667f);
    p = fmaf(p, y, 0.166666666667f);
    p = fmaf(p, y, 0.5f);
    p = fmaf(p, y, 1.0f);
    p = fmaf(p, y, 1.0f);
    return p * __int_as_float((i + 127) << 23);
}

// ---------------------------------------------------------------------------
// fp32 -> bf16 hi/lo split (vectorized, memory-bound)
// ---------------------------------------------------------------------------
__global__ void split_f32(const float* __restrict__ src, __nv_bfloat16* __restrict__ hi,
                          __nv_bfloat16* __restrict__ lo, int n4)
{
    int i = blockIdx.x * blockDim.x + threadIdx.x;
    if (i >= n4) return;
    float4 v = ((const float4*)src)[i];
    uint32_t h0, l0, h1, l1;
    split2(v.x, v.y, h0, l0);
    split2(v.z, v.w, h1, l1);
    ((uint2*)hi)[i] = make_uint2(h0, h1);
    ((uint2*)lo)[i] = make_uint2(l0, l1);
}

// ---------------------------------------------------------------------------
// mma.sync bf16x3 NT GEMM (128x128 tile, 8 warps, cp.async double-buffer)
// mode 0: fp32 row-major C
// mode 1: fp32 kv cache [B,H,2,S,D]  +  bf16 hi/lo scratch [B,H,S,D]
// mode 2: bf16 hi/lo scratch [B,H,S,D] only, scaled by QKSCALE (for Q)
// ---------------------------------------------------------------------------
#define KC 64
#define TILE_B  (128 * 128)
#define STAGE_B (4 * TILE_B)
#define NCHUNK  (HIDDIM / KC)     // 32

__global__ void __launch_bounds__(256, 1)
gemm_mma(const __nv_bfloat16* __restrict__ Ahi, const __nv_bfloat16* __restrict__ Alo,
         const __nv_bfloat16* __restrict__ Bhi, const __nv_bfloat16* __restrict__ Blo,
         float* __restrict__ C, int mode, int kvsel,
         __nv_bfloat16* __restrict__ Shi, __nv_bfloat16* __restrict__ Slo)
{
    extern __shared__ char dsm[];
    const int tid  = threadIdx.x;
    const int wid  = tid >> 5;
    const int lane = tid & 31;
    const int wm   = wid >> 2;
    const int wn   = wid & 3;
    const int bm = blockIdx.y * 128;
    const int bn = blockIdx.x * 128;
    const uint32_t smb = smem_u32(dsm);

    float acc[4][4][4];
#pragma unroll
    for (int mi = 0; mi < 4; mi++)
#pragma unroll
        for (int ni = 0; ni < 4; ni++)
#pragma unroll
            for (int t = 0; t < 4; t++) acc[mi][ni][t] = 0.f;

    const int lr = tid >> 3;
    const int lc = tid & 7;

    auto issue_stage = [&](int st, int kc) {
        char* s = dsm + st * STAGE_B;
        const size_t kb = (size_t)kc * KC;
#pragma unroll
        for (int it = 0; it < 4; it++) {
            int r = lr + it * 32;
            int sw = ((lc ^ (r & 7)) << 4);
            uint32_t so = smem_u32(s) + r * 128 + sw;
            size_t ga = (size_t)(bm + r) * HIDDIM + kb + lc * 8;
            size_t gb = (size_t)(bn + r) * HIDDIM + kb + lc * 8;
            cp_async16(so + 0 * TILE_B, Ahi + ga);
            cp_async16(so + 1 * TILE_B, Alo + ga);
            cp_async16(so + 2 * TILE_B, Bhi + gb);
            cp_async16(so + 3 * TILE_B, Blo + gb);
        }
        cp_commit();
    };

    issue_stage(0, 0);

    for (int kc = 0; kc < NCHUNK; kc++) {
        const int st = kc & 1;
        if (kc + 1 < NCHUNK) { issue_stage(st ^ 1, kc + 1); cp_wait<1>(); }
        else cp_wait<0>();
        __syncthreads();

        const uint32_t sb = smb + st * STAGE_B;
        const int arow_l = (lane & 15);
        const int koff_l = (lane >> 4);

#pragma unroll
        for (int ks = 0; ks < 4; ks++) {
            const int chunk = ks * 2 + koff_l;
            uint32_t ahi[4][4], alo[4][4];
#pragma unroll
            for (int mi = 0; mi < 4; mi++) {
                int r = wm * 64 + mi * 16 + arow_l;
                uint32_t off = (uint32_t)(r * 128 + ((chunk ^ (r & 7)) << 4));
                ldsm_x4(ahi[mi], sb + 0 * TILE_B + off);
                ldsm_x4(alo[mi], sb + 1 * TILE_B + off);
            }
            uint32_t bhi[4][2], blo[4][2];
#pragma unroll
            for (int g = 0; g < 2; g++) {
                int r = wn * 32 + g * 16 + arow_l;
                uint32_t off = (uint32_t)(r * 128 + ((chunk ^ (r & 7)) << 4));
                uint32_t t[4];
                ldsm_x4(t, sb + 2 * TILE_B + off);
                bhi[g * 2 + 0][0] = t[0]; bhi[g * 2 + 1][0] = t[1];
                bhi[g * 2 + 0][1] = t[2]; bhi[g * 2 + 1][1] = t[3];
                ldsm_x4(t, sb + 3 * TILE_B + off);
                blo[g * 2 + 0][0] = t[0]; blo[g * 2 + 1][0] = t[1];
                blo[g * 2 + 0][1] = t[2]; blo[g * 2 + 1][1] = t[3];
            }
#pragma unroll
            for (int mi = 0; mi < 4; mi++)
#pragma unroll
                for (int ni = 0; ni < 4; ni++) {
                    mma_16816(acc[mi][ni], ahi[mi], bhi[ni]);
                    mma_16816(acc[mi][ni], ahi[mi], blo[ni]);
                    mma_16816(acc[mi][ni], alo[mi], bhi[ni]);
                }
        }
        __syncthreads();
    }

    // epilogue
#pragma unroll
    for (int mi = 0; mi < 4; mi++) {
        const int row0 = bm + wm * 64 + mi * 16 + (lane >> 2);
#pragma unroll
        for (int half = 0; half < 2; half++) {
            const int row = row0 + half * 8;
            const int b = row >> 11, s = row & 2047;
#pragma unroll
            for (int ni = 0; ni < 4; ni++) {
                const int col = bn + wn * 32 + ni * 8 + (lane & 3) * 2;
                float v0 = acc[mi][ni][half * 2 + 0];
                float v1 = acc[mi][ni][half * 2 + 1];
                if (mode == 0) {
                    *(float2*)(C + (size_t)row * HIDDIM + col) = make_float2(v0, v1);
                } else {
                    const int h = col >> 7, d = col & 127;
                    const size_t sc = (((size_t)b * NH + h) * SEQ + s) * HDIM + d;
                    if (mode == 1) {
                        size_t kva = ((((size_t)b * NH + h) * 2 + kvsel) * SEQ + s) * HDIM + d;
                        *(float2*)(C + kva) = make_float2(v0, v1);
                    } else {
                        v0 *= QKSCALE; v1 *= QKSCALE;
                    }
                    uint32_t hw, lw;
                    split2(v0, v1, hw, lw);
                    *(uint32_t*)(Shi + sc) = hw;
                    *(uint32_t*)(Slo + sc) = lw;
                }
            }
        }
    }
}

// ---------------------------------------------------------------------------
// Tensor-core flash attention: causal, q-tile 128, k-tile 64, 8 warps.
// All operands pre-split bf16 hi/lo; Q pre-scaled. bf16x3 for QK and PV.
// smem: Qhi/Qlo 64KB @0/32768; 2 stages of {Khi,Klo,Vhi,Vlo} 64KB each.
// ---------------------------------------------------------------------------
#define FA_SMEM (65536 + 2 * 65536)   // 192 KB

__global__ void __launch_bounds__(256, 1)
flash_attn_tc(const __nv_bfloat16* __restrict__ Qhi, const __nv_bfloat16* __restrict__ Qlo,
              const __nv_bfloat16* __restrict__ Khi, const __nv_bfloat16* __restrict__ Klo,
              const __nv_bfloat16* __restrict__ Vhi, const __nv_bfloat16* __restrict__ Vlo,
              __nv_bfloat16* __restrict__ chi, __nv_bfloat16* __restrict__ clo)
{
    extern __shared__ char dsm[];
    const int tid = threadIdx.x, wid = tid >> 5, lane = tid & 31;
    const int qt = 15 - blockIdx.x;          // big tiles first
    const int bh = blockIdx.y;
    const uint32_t smb = smem_u32(dsm);
    const uint32_t sQh = smb, sQl = smb + 32768;

    const size_t bhb = (size_t)bh * SEQ * HDIM;
    const __nv_bfloat16* qh_g = Qhi + bhb + (size_t)qt * 128 * HDIM;
    const __nv_bfloat16* ql_g = Qlo + bhb + (size_t)qt * 128 * HDIM;

    // Q tile load (joins stage-0 commit group)
#pragma unroll
    for (int it = 0; it < 8; it++) {
        int idx = tid + it * 256;
        int r = idx >> 4, c = idx & 15;
        uint32_t off = r * 256 + ((c ^ (r & 7)) << 4);
        int g = r * 128 + c * 8;
        cp_async16(sQh + off, qh_g + g);
        cp_async16(sQl + off, ql_g + g);
    }

    auto load_kv = [&](int st, int kt) {
        uint32_t sb = smb + 65536 + st * 65536;
        const size_t tb = bhb + (size_t)kt * 64 * HDIM;
#pragma unroll
        for (int it = 0; it < 4; it++) {
            int idx = tid + it * 256;
            int r = idx >> 4, c = idx & 15;
            uint32_t off = r * 256 + ((c ^ (r & 7)) << 4);
            int g = r * 128 + c * 8;
            cp_async16(sb + off,         Khi + tb + g);
            cp_async16(sb + 16384 + off, Klo + tb + g);
            cp_async16(sb + 32768 + off, Vhi + tb + g);
            cp_async16(sb + 49152 + off, Vlo + tb + g);
        }
        cp_commit();
    };
    load_kv(0, 0);

    float o[16][4];
#pragma unroll
    for (int nb = 0; nb < 16; nb++)
#pragma unroll
        for (int t = 0; t < 4; t++) o[nb][t] = 0.f;
    float m0 = -INFINITY, m1 = -INFINITY, l0 = 0.f, l1 = 0.f;

    const int ktmax = 2 * qt + 1;
    for (int kt = 0; kt <= ktmax; kt++) {
        const int st = kt & 1;
        if (kt < ktmax) { load_kv(st ^ 1, kt + 1); cp_wait<1>(); }
        else cp_wait<0>();
        __syncthreads();

        const uint32_t sb = smb + 65536 + st * 65536;
        const uint32_t sKh = sb, sKl = sb + 16384, sVh = sb + 32768, sVl = sb + 49152;

        // ---- S = Q @ K^T (bf16x3) ----
        float s[8][4];
#pragma unroll
        for (int nb = 0; nb < 8; nb++)
#pragma unroll
            for (int t = 0; t < 4; t++) s[nb][t] = 0.f;

#pragma unroll
        for (int ks = 0; ks < 8; ks++) {
            const int c = ks * 2 + (lane >> 4);
            const int qr = wid * 16 + (lane & 15);
            uint32_t qoff = qr * 256 + ((c ^ (qr & 7)) << 4);
            uint32_t qh[4], ql[4];
            ldsm_x4(qh, sQh + qoff);
            ldsm_x4(ql, sQl + qoff);
#pragma unroll
            for (int g = 0; g < 4; g++) {
                int kr = g * 16 + (lane & 15);
                uint32_t koff = kr * 256 + ((c ^ (kr & 7)) << 4);
                uint32_t th[4], tl[4];
                ldsm_x4(th, sKh + koff);
                ldsm_x4(tl, sKl + koff);
                uint32_t b0h[2] = {th[0], th[2]}, b1h[2] = {th[1], th[3]};
                uint32_t b0l[2] = {tl[0], tl[2]}, b1l[2] = {tl[1], tl[3]};
                mma_16816(s[2 * g],     qh, b0h);
                mma_16816(s[2 * g],     qh, b0l);
                mma_16816(s[2 * g],     ql, b0h);
                mma_16816(s[2 * g + 1], qh, b1h);
                mma_16816(s[2 * g + 1], qh, b1l);
                mma_16816(s[2 * g + 1], ql, b1h);
            }
        }

        // ---- causal mask (only tiles on/after the diagonal band) ----
        if (kt >= 2 * qt) {
            const int q0 = qt * 128 + wid * 16 + (lane >> 2);
            const int k0 = kt * 64 + (lane & 3) * 2;
#pragma unroll
            for (int nb = 0; nb < 8; nb++)
#pragma unroll
                for (int t = 0; t < 4; t++) {
                    int kg = k0 + nb * 8 + (t & 1);
                    int qg = q0 + (t >> 1) * 8;
                    if (kg > qg) s[nb][t] = -INFINITY;
                }
        }

        // ---- online softmax (FFMA-pipe exp) ----
        float mx0 = -INFINITY, mx1 = -INFINITY;
#pragma unroll
        for (int nb = 0; nb < 8; nb++) {
            mx0 = fmaxf(mx0, fmaxf(s[nb][0], s[nb][1]));
            mx1 = fmaxf(mx1, fmaxf(s[nb][2], s[nb][3]));
        }
        mx0 = fmaxf(mx0, __shfl_xor_sync(0xffffffffu, mx0, 1));
        mx0 = fmaxf(mx0, __shfl_xor_sync(0xffffffffu, mx0, 2));
        mx1 = fmaxf(mx1, __shfl_xor_sync(0xffffffffu, mx1, 1));
        mx1 = fmaxf(mx1, __shfl_xor_sync(0xffffffffu, mx1, 2));
        float mn0 = fmaxf(m0, mx0), mn1 = fmaxf(m1, mx1);
        float c0 = fexp(m0 - mn0), c1 = fexp(m1 - mn1);
        m0 = mn0; m1 = mn1;

        float rs0 = 0.f, rs1 = 0.f;
#pragma unroll
        for (int nb = 0; nb < 8; nb++) {
            s[nb][0] = fexp(s[nb][0] - mn0);
            s[nb][1] = fexp(s[nb][1] - mn0);
            s[nb][2] = fexp(s[nb][2] - mn1);
            s[nb][3] = fexp(s[nb][3] - mn1);
            rs0 += s[nb][0] + s[nb][1];
            rs1 += s[nb][2] + s[nb][3];
        }
        rs0 += __shfl_xor_sync(0xffffffffu, rs0, 1);
        rs0 += __shfl_xor_sync(0xffffffffu, rs0, 2);
        rs1 += __shfl_xor_sync(0xffffffffu, rs1, 1);
        rs1 += __shfl_xor_sync(0xffffffffu, rs1, 2);
        l0 = l0 * c0 + rs0;
        l1 = l1 * c1 + rs1;
#pragma unroll
        for (int nb = 0; nb < 16; nb++) {
            o[nb][0] *= c0; o[nb][1] *= c0;
            o[nb][2] *= c1; o[nb][3] *= c1;
        }

        // ---- P -> bf16 hi/lo A-fragments ----
        uint32_t ph[4][4], pl[4][4];
#pragma unroll
        for (int j = 0; j < 4; j++) {
            split2(s[2 * j][0],     s[2 * j][1],     ph[j][0], pl[j][0]);
            split2(s[2 * j][2],     s[2 * j][3],     ph[j][1], pl[j][1]);
            split2(s[2 * j + 1][0], s[2 * j + 1][1], ph[j][2], pl[j][2]);
            split2(s[2 * j + 1][2], s[2 * j + 1][3], ph[j][3], pl[j][3]);
        }

        // ---- O += P @ V (bf16x3, V via ldmatrix.trans) ----
#pragma unroll
        for (int ks = 0; ks < 4; ks++) {
            const int vr = ks * 16 + (lane & 15);
#pragma unroll
            for (int db = 0; db < 8; db++) {
                const int c = db * 2 + (lane >> 4);
                uint32_t voff = vr * 256 + ((c ^ (vr & 7)) << 4);
                uint32_t th[4], tl[4];
                ldsm_x4_t(th, sVh + voff);
                ldsm_x4_t(tl, sVl + voff);
                uint32_t b0h[2] = {th[0], th[1]}, b1h[2] = {th[2], th[3]};
                uint32_t b0l[2] = {tl[0], tl[1]}, b1l[2] = {tl[2], tl[3]};
                mma_16816(o[2 * db],     ph[ks], b0h);
                mma_16816(o[2 * db],     ph[ks], b0l);
                mma_16816(o[2 * db],     pl[ks], b0h);
                mma_16816(o[2 * db + 1], ph[ks], b1h);
                mma_16816(o[2 * db + 1], ph[ks], b1l);
                mma_16816(o[2 * db + 1], pl[ks], b1h);
            }
        }
        __syncthreads();
    }

    // epilogue: ctx[b, s, h*128+d] as bf16 hi/lo
    const int b = bh >> 4, h = bh & 15;
    const float i0 = 1.f / l0, i1 = 1.f / l1;
    const int r0 = qt * 128 + wid * 16 + (lane >> 2);
#pragma unroll
    for (int half = 0; half < 2; half++) {
        const int srow = r0 + half * 8;
        const float inv = half ? i1 : i0;
        const size_t base = ((size_t)b * SEQ + srow) * HIDDIM + (size_t)h * HDIM + (lane & 3) * 2;
#pragma unroll
        for (int nb = 0; nb < 16; nb++) {
            uint32_t hw, lw;
            split2(o[nb][half * 2] * inv, o[nb][half * 2 + 1] * inv, hw, lw);
            *(uint32_t*)(chi + base + nb * 8) = hw;
            *(uint32_t*)(clo + base + nb * 8) = lw;
        }
    }
}

// ---------------------------------------------------------------------------
extern "C" void kernel_launch(void* const* d_in, const int* in_sizes, int n_in,
                              void* d_out, int out_size)
{
    const float* x  = (const float*)d_in[0];
    const float* Wq = (const float*)d_in[1];
    const float* Wk = (const float*)d_in[2];
    const float* Wv = (const float*)d_in[3];
    const float* Wo = (const float*)d_in[4];

    float* out = (float*)d_out;                          // [B,S,HID]
    float* kv  = out + (size_t)BSZ * SEQ * HIDDIM;       // [B,H,2,S,D]

    __nv_bfloat16 *xhi, *xlo, *whi, *wlo, *chi, *clo;
    __nv_bfloat16 *qhi, *qlo, *khi, *klo, *vhi, *vlo;
    cudaGetSymbolAddress((void**)&xhi, g_xhi);
    cudaGetSymbolAddress((void**)&xlo, g_xlo);
    cudaGetSymbolAddress((void**)&whi, g_whi);
    cudaGetSymbolAddress((void**)&wlo, g_wlo);
    cudaGetSymbolAddress((void**)&chi, g_chi);
    cudaGetSymbolAddress((void**)&clo, g_clo);
    cudaGetSymbolAddress((void**)&qhi, g_qhi);
    cudaGetSymbolAddress((void**)&qlo, g_qlo);
    cudaGetSymbolAddress((void**)&khi, g_khi);
    cudaGetSymbolAddress((void**)&klo, g_klo);
    cudaGetSymbolAddress((void**)&vhi, g_vhi);
    cudaGetSymbolAddress((void**)&vlo, g_vlo);

    const size_t WN = (size_t)HIDDIM * HIDDIM;

    // input splits
    {
        int n4x = (int)((size_t)MTOT * HIDDIM / 4);
        split_f32<<<(n4x + 255) / 256, 256>>>(x, xhi, xlo, n4x);
        int n4w = (int)(WN / 4);
        split_f32<<<(n4w + 255) / 256, 256>>>(Wq, whi + 0 * WN, wlo + 0 * WN, n4w);
        split_f32<<<(n4w + 255) / 256, 256>>>(Wk, whi + 1 * WN, wlo + 1 * WN, n4w);
        split_f32<<<(n4w + 255) / 256, 256>>>(Wv, whi + 2 * WN, wlo + 2 * WN, n4w);
        split_f32<<<(n4w + 255) / 256, 256>>>(Wo, whi + 3 * WN, wlo + 3 * WN, n4w);
    }

    // projections (Q pre-scaled + pre-split; K/V dual-write fp32 kv + bf16 split)
    const int gsmem = 2 * STAGE_B;
    cudaFuncSetAttribute(gemm_mma, cudaFuncAttributeMaxDynamicSharedMemorySize, gsmem);
    dim3 ggrid(HIDDIM / 128, MTOT / 128);
    gemm_mma<<<ggrid, 256, gsmem>>>(xhi, xlo, whi + 0 * WN, wlo + 0 * WN, out, 2, 0, qhi, qlo);
    gemm_mma<<<ggrid, 256, gsmem>>>(xhi, xlo, whi + 1 * WN, wlo + 1 * WN, kv, 1, 0, khi, klo);
    gemm_mma<<<ggrid, 256, gsmem>>>(xhi, xlo, whi + 2 * WN, wlo + 2 * WN, kv, 1, 1, vhi, vlo);

    // tensor-core flash attention
    cudaFuncSetAttribute(flash_attn_tc, cudaFuncAttributeMaxDynamicSharedMemorySize, FA_SMEM);
    flash_attn_tc<<<dim3(SEQ / 128, BSZ * NH), 256, FA_SMEM>>>(
        qhi, qlo, khi, klo, vhi, vlo, chi, clo);

    // output projection
    gemm_mma<<<ggrid, 256, gsmem>>>(chi, clo, whi + 3 * WN, wlo + 3 * WN, out, 0, 0, nullptr, nullptr);
}

// round 13
// speedup vs baseline: 3.9765x; 1.0135x over previous
#include <cuda_runtime.h>
#include <cuda_bf16.h>
#include <math.h>
#include <stdint.h>

#define BSZ 4
#define SEQ 2048
#define HIDDIM 2048
#define NH 16
#define HDIM 128
#define MTOT (BSZ * SEQ)   // 8192
#define QKSCALE 0.08838834764831845f
// exp2-domain: fold log2(e) into the Q scale so softmax uses 2^x
#define QSCALE2 (QKSCALE * 1.4426950408889634f)

// ---------------------------------------------------------------------------
// Scratch (static __device__ — no allocations allowed)
// ---------------------------------------------------------------------------
__device__ __nv_bfloat16 g_xhi[(size_t)MTOT * HIDDIM];
__device__ __nv_bfloat16 g_xlo[(size_t)MTOT * HIDDIM];
__device__ __nv_bfloat16 g_whi[(size_t)4 * HIDDIM * HIDDIM];   // [Wq|Wk|Wv|Wo]
__device__ __nv_bfloat16 g_wlo[(size_t)4 * HIDDIM * HIDDIM];
__device__ __nv_bfloat16 g_chi[(size_t)MTOT * HIDDIM];
__device__ __nv_bfloat16 g_clo[(size_t)MTOT * HIDDIM];
__device__ __nv_bfloat16 g_qhi[(size_t)MTOT * HIDDIM];         // [B,H,S,D] log2-scaled
__device__ __nv_bfloat16 g_qlo[(size_t)MTOT * HIDDIM];
__device__ __nv_bfloat16 g_khi[(size_t)MTOT * HIDDIM];
__device__ __nv_bfloat16 g_klo[(size_t)MTOT * HIDDIM];
__device__ __nv_bfloat16 g_vhi[(size_t)MTOT * HIDDIM];
__device__ __nv_bfloat16 g_vlo[(size_t)MTOT * HIDDIM];

// ---------------------------------------------------------------------------
// Portable (compute_80+) tensor-core helpers
// ---------------------------------------------------------------------------
__device__ __forceinline__ uint32_t smem_u32(const void* p) {
    uint32_t a;
    asm("{ .reg .u64 t; cvta.to.shared.u64 t, %1; cvt.u32.u64 %0, t; }" : "=r"(a) : "l"(p));
    return a;
}
__device__ __forceinline__ void cp_async16(uint32_t dst, const void* src) {
    asm volatile("cp.async.cg.shared.global [%0], [%1], 16;" :: "r"(dst), "l"(src) : "memory");
}
__device__ __forceinline__ void cp_commit() {
    asm volatile("cp.async.commit_group;" ::: "memory");
}
template <int N>
__device__ __forceinline__ void cp_wait() {
    asm volatile("cp.async.wait_group %0;" :: "n"(N) : "memory");
}
__device__ __forceinline__ void ldsm_x4(uint32_t* r, uint32_t addr) {
    asm volatile("ldmatrix.sync.aligned.m8n8.x4.shared.b16 {%0,%1,%2,%3}, [%4];"
                 : "=r"(r[0]), "=r"(r[1]), "=r"(r[2]), "=r"(r[3]) : "r"(addr));
}
__device__ __forceinline__ void ldsm_x4_t(uint32_t* r, uint32_t addr) {
    asm volatile("ldmatrix.sync.aligned.m8n8.x4.trans.shared.b16 {%0,%1,%2,%3}, [%4];"
                 : "=r"(r[0]), "=r"(r[1]), "=r"(r[2]), "=r"(r[3]) : "r"(addr));
}
__device__ __forceinline__ void mma_16816(float* c, const uint32_t* a, const uint32_t* b) {
    asm volatile(
        "mma.sync.aligned.m16n8k16.row.col.f32.bf16.bf16.f32 "
        "{%0,%1,%2,%3}, {%4,%5,%6,%7}, {%8,%9}, {%0,%1,%2,%3};"
        : "+f"(c[0]), "+f"(c[1]), "+f"(c[2]), "+f"(c[3])
        : "r"(a[0]), "r"(a[1]), "r"(a[2]), "r"(a[3]), "r"(b[0]), "r"(b[1]));
}

__device__ __forceinline__ void split2(float a, float b, uint32_t& hi, uint32_t& lo) {
    __nv_bfloat16 ha = __float2bfloat16_rn(a), hb = __float2bfloat16_rn(b);
    __nv_bfloat16 la = __float2bfloat16_rn(a - __bfloat162float(ha));
    __nv_bfloat16 lb = __float2bfloat16_rn(b - __bfloat162float(hb));
    hi = (uint32_t)__bfloat16_as_ushort(ha) | ((uint32_t)__bfloat16_as_ushort(hb) << 16);
    lo = (uint32_t)__bfloat16_as_ushort(la) | ((uint32_t)__bfloat16_as_ushort(lb) << 16);
}

// FFMA-pipe 2^x (no MUFU): x <= ~0, handles -inf via clamp. rel err ~1e-7.
__device__ __forceinline__ float fexp2(float t) {
    t = fmaxf(t, -126.0f);
    float fi = t + 12582912.0f;               // round-to-nearest int
    int i = __float_as_int(fi) - 0x4B400000;
    float r = t - (fi - 12582912.0f);         // r in [-0.5, 0.5]
    float p = 1.8775767e-3f;
    p = fmaf(p, r, 8.9893397e-3f);
    p = fmaf(p, r, 5.5826318e-2f);
    p = fmaf(p, r, 2.4015361e-1f);
    p = fmaf(p, r, 6.9315308e-1f);
    p = fmaf(p, r, 1.0f);                     // p(0) == 1 exactly
    return p * __int_as_float((i + 127) << 23);
}

// ---------------------------------------------------------------------------
// fp32 -> bf16 hi/lo splits
// ---------------------------------------------------------------------------
__global__ void split_f32(const float* __restrict__ src, __nv_bfloat16* __restrict__ hi,
                          __nv_bfloat16* __restrict__ lo, int n4)
{
    int i = blockIdx.x * blockDim.x + threadIdx.x;
    if (i >= n4) return;
    float4 v = ((const float4*)src)[i];
    uint32_t h0, l0, h1, l1;
    split2(v.x, v.y, h0, l0);
    split2(v.z, v.w, h1, l1);
    ((uint2*)hi)[i] = make_uint2(h0, h1);
    ((uint2*)lo)[i] = make_uint2(l0, l1);
}

// all four weights in one launch -> contiguous [Wq|Wk|Wv|Wo] hi/lo
__global__ void split_w4(const float* __restrict__ Wq, const float* __restrict__ Wk,
                         const float* __restrict__ Wv, const float* __restrict__ Wo,
                         __nv_bfloat16* __restrict__ hi, __nv_bfloat16* __restrict__ lo)
{
    const int per = (HIDDIM * HIDDIM) / 4;           // float4 per weight
    int i = blockIdx.x * blockDim.x + threadIdx.x;   // 0 .. 4*per-1
    int w = i / per, j = i - w * per;
    const float* src = (w == 0) ? Wq : (w == 1) ? Wk : (w == 2) ? Wv : Wo;
    float4 v = ((const float4*)src)[j];
    uint32_t h0, l0, h1, l1;
    split2(v.x, v.y, h0, l0);
    split2(v.z, v.w, h1, l1);
    ((uint2*)hi)[i] = make_uint2(h0, h1);
    ((uint2*)lo)[i] = make_uint2(l0, l1);
}

// ---------------------------------------------------------------------------
// mma.sync bf16x3 NT GEMM, 128x128 tile, 8 warps, 3-stage cp.async pipeline,
// single __syncthreads per K-iteration.
// mode 0: fp32 row-major C [M, HIDDIM]
// mode 3: merged QKV (N=6144): sel=col>>11 -> 0:q (scaled, bf16 split only),
//         1:k (fp32 kv cache + split), 2:v (fp32 kv cache + split)
// ---------------------------------------------------------------------------
#define KC 64
#define TILE_B  (128 * 128)
#define STAGE_B (4 * TILE_B)          // 64 KB
#define NCHUNK  (HIDDIM / KC)         // 32

__global__ void __launch_bounds__(256, 1)
gemm_mma(const __nv_bfloat16* __restrict__ Ahi, const __nv_bfloat16* __restrict__ Alo,
         const __nv_bfloat16* __restrict__ Bhi, const __nv_bfloat16* __restrict__ Blo,
         float* __restrict__ C, int mode,
         __nv_bfloat16* __restrict__ qhi, __nv_bfloat16* __restrict__ qlo,
         __nv_bfloat16* __restrict__ khi, __nv_bfloat16* __restrict__ klo,
         __nv_bfloat16* __restrict__ vhi, __nv_bfloat16* __restrict__ vlo)
{
    extern __shared__ char dsm[];
    const int tid  = threadIdx.x;
    const int wid  = tid >> 5;
    const int lane = tid & 31;
    const int wm   = wid >> 2;
    const int wn   = wid & 3;
    const int bm = blockIdx.y * 128;
    const int bn = blockIdx.x * 128;
    const uint32_t smb = smem_u32(dsm);

    float acc[4][4][4];
#pragma unroll
    for (int mi = 0; mi < 4; mi++)
#pragma unroll
        for (int ni = 0; ni < 4; ni++)
#pragma unroll
            for (int t = 0; t < 4; t++) acc[mi][ni][t] = 0.f;

    const int lr = tid >> 3;
    const int lc = tid & 7;

    auto issue_stage = [&](int st, int kc) {
        uint32_t sbase = smb + st * STAGE_B;
        const size_t kb = (size_t)kc * KC;
#pragma unroll
        for (int it = 0; it < 4; it++) {
            int r = lr + it * 32;
            int sw = ((lc ^ (r & 7)) << 4);
            uint32_t so = sbase + r * 128 + sw;
            size_t ga = (size_t)(bm + r) * HIDDIM + kb + lc * 8;
            size_t gb = (size_t)(bn + r) * HIDDIM + kb + lc * 8;
            cp_async16(so + 0 * TILE_B, Ahi + ga);
            cp_async16(so + 1 * TILE_B, Alo + ga);
            cp_async16(so + 2 * TILE_B, Bhi + gb);
            cp_async16(so + 3 * TILE_B, Blo + gb);
        }
        cp_commit();
    };

    issue_stage(0, 0);
    issue_stage(1, 1);

    int cs = 0, is = 2;                     // compute stage, issue stage
    for (int kc = 0; kc < NCHUNK; kc++) {
        if (kc + 1 < NCHUNK) cp_wait<1>(); else cp_wait<0>();
        __syncthreads();                    // visibility + stage-retire barrier
        if (kc + 2 < NCHUNK) issue_stage(is, kc + 2);

        const uint32_t sb = smb + cs * STAGE_B;
        const int arow_l = (lane & 15);
        const int koff_l = (lane >> 4);

#pragma unroll
        for (int ks = 0; ks < 4; ks++) {
            const int chunk = ks * 2 + koff_l;
            uint32_t ahi[4][4], alo[4][4];
#pragma unroll
            for (int mi = 0; mi < 4; mi++) {
                int r = wm * 64 + mi * 16 + arow_l;
                uint32_t off = (uint32_t)(r * 128 + ((chunk ^ (r & 7)) << 4));
                ldsm_x4(ahi[mi], sb + 0 * TILE_B + off);
                ldsm_x4(alo[mi], sb + 1 * TILE_B + off);
            }
            uint32_t bhi[4][2], blo[4][2];
#pragma unroll
            for (int g = 0; g < 2; g++) {
                int r = wn * 32 + g * 16 + arow_l;
                uint32_t off = (uint32_t)(r * 128 + ((chunk ^ (r & 7)) << 4));
                uint32_t t[4];
                ldsm_x4(t, sb + 2 * TILE_B + off);
                bhi[g * 2 + 0][0] = t[0]; bhi[g * 2 + 1][0] = t[1];
                bhi[g * 2 + 0][1] = t[2]; bhi[g * 2 + 1][1] = t[3];
                ldsm_x4(t, sb + 3 * TILE_B + off);
                blo[g * 2 + 0][0] = t[0]; blo[g * 2 + 1][0] = t[1];
                blo[g * 2 + 0][1] = t[2]; blo[g * 2 + 1][1] = t[3];
            }
#pragma unroll
            for (int mi = 0; mi < 4; mi++)
#pragma unroll
                for (int ni = 0; ni < 4; ni++) {
                    mma_16816(acc[mi][ni], ahi[mi], bhi[ni]);
                    mma_16816(acc[mi][ni], ahi[mi], blo[ni]);
                    mma_16816(acc[mi][ni], alo[mi], bhi[ni]);
                }
        }
        cs = (cs == 2) ? 0 : cs + 1;
        is = (is == 2) ? 0 : is + 1;
    }

    // epilogue
#pragma unroll
    for (int mi = 0; mi < 4; mi++) {
        const int row0 = bm + wm * 64 + mi * 16 + (lane >> 2);
#pragma unroll
        for (int half = 0; half < 2; half++) {
            const int row = row0 + half * 8;
            const int b = row >> 11, s = row & 2047;
#pragma unroll
            for (int ni = 0; ni < 4; ni++) {
                const int col = bn + wn * 32 + ni * 8 + (lane & 3) * 2;
                float v0 = acc[mi][ni][half * 2 + 0];
                float v1 = acc[mi][ni][half * 2 + 1];
                if (mode == 0) {
                    *(float2*)(C + (size_t)row * HIDDIM + col) = make_float2(v0, v1);
                } else {
                    const int sel = col >> 11;          // 0 q, 1 k, 2 v
                    const int cm = col & 2047;
                    const int h = cm >> 7, d = cm & 127;
                    const size_t sc = (((size_t)b * NH + h) * SEQ + s) * HDIM + d;
                    uint32_t hw, lw;
                    if (sel == 0) {
                        split2(v0 * QSCALE2, v1 * QSCALE2, hw, lw);
                        *(uint32_t*)(qhi + sc) = hw;
                        *(uint32_t*)(qlo + sc) = lw;
                    } else {
                        size_t kva = ((((size_t)b * NH + h) * 2 + (sel - 1)) * SEQ + s) * HDIM + d;
                        *(float2*)(C + kva) = make_float2(v0, v1);
                        split2(v0, v1, hw, lw);
                        __nv_bfloat16* sh = (sel == 1) ? khi : vhi;
                        __nv_bfloat16* sl = (sel == 1) ? klo : vlo;
                        *(uint32_t*)(sh + sc) = hw;
                        *(uint32_t*)(sl + sc) = lw;
                    }
                }
            }
        }
    }
}

// ---------------------------------------------------------------------------
// Tensor-core flash attention: causal, q-tile 128, k-tile 64, 8 warps,
// exp2-domain online softmax, single __syncthreads per k-tile.
// ---------------------------------------------------------------------------
#define FA_SMEM (65536 + 2 * 65536)   // 192 KB

__global__ void __launch_bounds__(256, 1)
flash_attn_tc(const __nv_bfloat16* __restrict__ Qhi, const __nv_bfloat16* __restrict__ Qlo,
              const __nv_bfloat16* __restrict__ Khi, const __nv_bfloat16* __restrict__ Klo,
              const __nv_bfloat16* __restrict__ Vhi, const __nv_bfloat16* __restrict__ Vlo,
              __nv_bfloat16* __restrict__ chi, __nv_bfloat16* __restrict__ clo)
{
    extern __shared__ char dsm[];
    const int tid = threadIdx.x, wid = tid >> 5, lane = tid & 31;
    const int qt = 15 - blockIdx.x;          // big tiles first
    const int bh = blockIdx.y;
    const uint32_t smb = smem_u32(dsm);
    const uint32_t sQh = smb, sQl = smb + 32768;

    const size_t bhb = (size_t)bh * SEQ * HDIM;
    const __nv_bfloat16* qh_g = Qhi + bhb + (size_t)qt * 128 * HDIM;
    const __nv_bfloat16* ql_g = Qlo + bhb + (size_t)qt * 128 * HDIM;

    // Q tile load (joins stage-0 commit group)
#pragma unroll
    for (int it = 0; it < 8; it++) {
        int idx = tid + it * 256;
        int r = idx >> 4, c = idx & 15;
        uint32_t off = r * 256 + ((c ^ (r & 7)) << 4);
        int g = r * 128 + c * 8;
        cp_async16(sQh + off, qh_g + g);
        cp_async16(sQl + off, ql_g + g);
    }

    auto load_kv = [&](int st, int kt) {
        uint32_t sb = smb + 65536 + st * 65536;
        const size_t tb = bhb + (size_t)kt * 64 * HDIM;
#pragma unroll
        for (int it = 0; it < 4; it++) {
            int idx = tid + it * 256;
            int r = idx >> 4, c = idx & 15;
            uint32_t off = r * 256 + ((c ^ (r & 7)) << 4);
            int g = r * 128 + c * 8;
            cp_async16(sb + off,         Khi + tb + g);
            cp_async16(sb + 16384 + off, Klo + tb + g);
            cp_async16(sb + 32768 + off, Vhi + tb + g);
            cp_async16(sb + 49152 + off, Vlo + tb + g);
        }
        cp_commit();
    };
    load_kv(0, 0);

    float o[16][4];
#pragma unroll
    for (int nb = 0; nb < 16; nb++)
#pragma unroll
        for (int t = 0; t < 4; t++) o[nb][t] = 0.f;
    float m0 = -INFINITY, m1 = -INFINITY, l0 = 0.f, l1 = 0.f;

    const int ktmax = 2 * qt + 1;
    for (int kt = 0; kt <= ktmax; kt++) {
        const int st = kt & 1;
        cp_wait<0>();
        __syncthreads();
        if (kt < ktmax) load_kv(st ^ 1, kt + 1);

        const uint32_t sb = smb + 65536 + st * 65536;
        const uint32_t sKh = sb, sKl = sb + 16384, sVh = sb + 32768, sVl = sb + 49152;

        // ---- S = Q @ K^T (bf16x3, log2-scaled) ----
        float s[8][4];
#pragma unroll
        for (int nb = 0; nb < 8; nb++)
#pragma unroll
            for (int t = 0; t < 4; t++) s[nb][t] = 0.f;

#pragma unroll
        for (int ks = 0; ks < 8; ks++) {
            const int c = ks * 2 + (lane >> 4);
            const int qr = wid * 16 + (lane & 15);
            uint32_t qoff = qr * 256 + ((c ^ (qr & 7)) << 4);
            uint32_t qh[4], ql[4];
            ldsm_x4(qh, sQh + qoff);
            ldsm_x4(ql, sQl + qoff);
#pragma unroll
            for (int g = 0; g < 4; g++) {
                int kr = g * 16 + (lane & 15);
                uint32_t koff = kr * 256 + ((c ^ (kr & 7)) << 4);
                uint32_t th[4], tl[4];
                ldsm_x4(th, sKh + koff);
                ldsm_x4(tl, sKl + koff);
                uint32_t b0h[2] = {th[0], th[2]}, b1h[2] = {th[1], th[3]};
                uint32_t b0l[2] = {tl[0], tl[2]}, b1l[2] = {tl[1], tl[3]};
                mma_16816(s[2 * g],     qh, b0h);
                mma_16816(s[2 * g],     qh, b0l);
                mma_16816(s[2 * g],     ql, b0h);
                mma_16816(s[2 * g + 1], qh, b1h);
                mma_16816(s[2 * g + 1], qh, b1l);
                mma_16816(s[2 * g + 1], ql, b1h);
            }
        }

        // ---- causal mask (diagonal band only) ----
        if (kt >= 2 * qt) {
            const int q0 = qt * 128 + wid * 16 + (lane >> 2);
            const int k0 = kt * 64 + (lane & 3) * 2;
#pragma unroll
            for (int nb = 0; nb < 8; nb++)
#pragma unroll
                for (int t = 0; t < 4; t++) {
                    int kg = k0 + nb * 8 + (t & 1);
                    int qg = q0 + (t >> 1) * 8;
                    if (kg > qg) s[nb][t] = -INFINITY;
                }
        }

        // ---- online softmax in exp2 domain ----
        float mx0 = -INFINITY, mx1 = -INFINITY;
#pragma unroll
        for (int nb = 0; nb < 8; nb++) {
            mx0 = fmaxf(mx0, fmaxf(s[nb][0], s[nb][1]));
            mx1 = fmaxf(mx1, fmaxf(s[nb][2], s[nb][3]));
        }
        mx0 = fmaxf(mx0, __shfl_xor_sync(0xffffffffu, mx0, 1));
        mx0 = fmaxf(mx0, __shfl_xor_sync(0xffffffffu, mx0, 2));
        mx1 = fmaxf(mx1, __shfl_xor_sync(0xffffffffu, mx1, 1));
        mx1 = fmaxf(mx1, __shfl_xor_sync(0xffffffffu, mx1, 2));
        float mn0 = fmaxf(m0, mx0), mn1 = fmaxf(m1, mx1);

        // rescale skip: once running max stops growing (common), c==1 exactly
        bool need = !__all_sync(0xffffffffu, (m0 == mn0) && (m1 == mn1));
        if (need) {
            float c0 = fexp2(m0 - mn0), c1 = fexp2(m1 - mn1);
            l0 *= c0; l1 *= c1;
#pragma unroll
            for (int nb = 0; nb < 16; nb++) {
                o[nb][0] *= c0; o[nb][1] *= c0;
                o[nb][2] *= c1; o[nb][3] *= c1;
            }
            m0 = mn0; m1 = mn1;
        }

        float rs0 = 0.f, rs1 = 0.f;
#pragma unroll
        for (int nb = 0; nb < 8; nb++) {
            s[nb][0] = fexp2(s[nb][0] - m0);
            s[nb][1] = fexp2(s[nb][1] - m0);
            s[nb][2] = fexp2(s[nb][2] - m1);
            s[nb][3] = fexp2(s[nb][3] - m1);
            rs0 += s[nb][0] + s[nb][1];
            rs1 += s[nb][2] + s[nb][3];
        }
        rs0 += __shfl_xor_sync(0xffffffffu, rs0, 1);
        rs0 += __shfl_xor_sync(0xffffffffu, rs0, 2);
        rs1 += __shfl_xor_sync(0xffffffffu, rs1, 1);
        rs1 += __shfl_xor_sync(0xffffffffu, rs1, 2);
        l0 += rs0;
        l1 += rs1;

        // ---- P -> bf16 hi/lo A-fragments ----
        uint32_t ph[4][4], pl[4][4];
#pragma unroll
        for (int j = 0; j < 4; j++) {
            split2(s[2 * j][0],     s[2 * j][1],     ph[j][0], pl[j][0]);
            split2(s[2 * j][2],     s[2 * j][3],     ph[j][1], pl[j][1]);
            split2(s[2 * j + 1][0], s[2 * j + 1][1], ph[j][2], pl[j][2]);
            split2(s[2 * j + 1][2], s[2 * j + 1][3], ph[j][3], pl[j][3]);
        }

        // ---- O += P @ V (bf16x3, V via ldmatrix.trans) ----
#pragma unroll
        for (int ks = 0; ks < 4; ks++) {
            const int vr = ks * 16 + (lane & 15);
#pragma unroll
            for (int db = 0; db < 8; db++) {
                const int c = db * 2 + (lane >> 4);
                uint32_t voff = vr * 256 + ((c ^ (vr & 7)) << 4);
                uint32_t th[4], tl[4];
                ldsm_x4_t(th, sVh + voff);
                ldsm_x4_t(tl, sVl + voff);
                uint32_t b0h[2] = {th[0], th[1]}, b1h[2] = {th[2], th[3]};
                uint32_t b0l[2] = {tl[0], tl[1]}, b1l[2] = {tl[2], tl[3]};
                mma_16816(o[2 * db],     ph[ks], b0h);
                mma_16816(o[2 * db],     ph[ks], b0l);
                mma_16816(o[2 * db],     pl[ks], b0h);
                mma_16816(o[2 * db + 1], ph[ks], b1h);
                mma_16816(o[2 * db + 1], ph[ks], b1l);
                mma_16816(o[2 * db + 1], pl[ks], b1h);
            }
        }
    }

    // epilogue: ctx[b, s, h*128+d] as bf16 hi/lo
    const int b = bh >> 4, h = bh & 15;
    const float i0 = 1.f / l0, i1 = 1.f / l1;
    const int r0 = qt * 128 + wid * 16 + (lane >> 2);
#pragma unroll
    for (int half = 0; half < 2; half++) {
        const int srow = r0 + half * 8;
        const float inv = half ? i1 : i0;
        const size_t base = ((size_t)b * SEQ + srow) * HIDDIM + (size_t)h * HDIM + (lane & 3) * 2;
#pragma unroll
        for (int nb = 0; nb < 16; nb++) {
            uint32_t hw, lw;
            split2(o[nb][half * 2] * inv, o[nb][half * 2 + 1] * inv, hw, lw);
            *(uint32_t*)(chi + base + nb * 8) = hw;
            *(uint32_t*)(clo + base + nb * 8) = lw;
        }
    }
}

// ---------------------------------------------------------------------------
extern "C" void kernel_launch(void* const* d_in, const int* in_sizes, int n_in,
                              void* d_out, int out_size)
{
    const float* x  = (const float*)d_in[0];
    const float* Wq = (const float*)d_in[1];
    const float* Wk = (const float*)d_in[2];
    const float* Wv = (const float*)d_in[3];
    const float* Wo = (const float*)d_in[4];

    float* out = (float*)d_out;                          // [B,S,HID]
    float* kv  = out + (size_t)BSZ * SEQ * HIDDIM;       // [B,H,2,S,D]

    __nv_bfloat16 *xhi, *xlo, *whi, *wlo, *chi, *clo;
    __nv_bfloat16 *qhi, *qlo, *khi, *klo, *vhi, *vlo;
    cudaGetSymbolAddress((void**)&xhi, g_xhi);
    cudaGetSymbolAddress((void**)&xlo, g_xlo);
    cudaGetSymbolAddress((void**)&whi, g_whi);
    cudaGetSymbolAddress((void**)&wlo, g_wlo);
    cudaGetSymbolAddress((void**)&chi, g_chi);
    cudaGetSymbolAddress((void**)&clo, g_clo);
    cudaGetSymbolAddress((void**)&qhi, g_qhi);
    cudaGetSymbolAddress((void**)&qlo, g_qlo);
    cudaGetSymbolAddress((void**)&khi, g_khi);
    cudaGetSymbolAddress((void**)&klo, g_klo);
    cudaGetSymbolAddress((void**)&vhi, g_vhi);
    cudaGetSymbolAddress((void**)&vlo, g_vlo);

    const size_t WN = (size_t)HIDDIM * HIDDIM;

    // splits: x + all 4 weights (2 launches)
    {
        int n4x = (int)((size_t)MTOT * HIDDIM / 4);
        split_f32<<<(n4x + 255) / 256, 256>>>(x, xhi, xlo, n4x);
        int n4w = (int)(4 * WN / 4);
        split_w4<<<(n4w + 255) / 256, 256>>>(Wq, Wk, Wv, Wo, whi, wlo);
    }

    const int gsmem = 3 * STAGE_B;                       // 192 KB
    cudaFuncSetAttribute(gemm_mma, cudaFuncAttributeMaxDynamicSharedMemorySize, gsmem);

    // merged QKV projection: N = 6144 (weights [Wq|Wk|Wv] are row-contiguous)
    dim3 qkvgrid(3 * HIDDIM / 128, MTOT / 128);          // (48, 64)
    gemm_mma<<<qkvgrid, 256, gsmem>>>(xhi, xlo, whi, wlo, kv, 3,
                                      qhi, qlo, khi, klo, vhi, vlo);

    // tensor-core flash attention (exp2 domain)
    cudaFuncSetAttribute(flash_attn_tc, cudaFuncAttributeMaxDynamicSharedMemorySize, FA_SMEM);
    flash_attn_tc<<<dim3(SEQ / 128, BSZ * NH), 256, FA_SMEM>>>(
        qhi, qlo, khi, klo, vhi, vlo, chi, clo);

    // output projection
    dim3 ogrid(HIDDIM / 128, MTOT / 128);                // (16, 64)
    gemm_mma<<<ogrid, 256, gsmem>>>(chi, clo, whi + 3 * WN, wlo + 3 * WN, out, 0,
                                    nullptr, nullptr, nullptr, nullptr, nullptr, nullptr);
}